// round 16
// baseline (speedup 1.0000x reference)
#include <cuda_runtime.h>
#include <cstdint>

#define NB 8
#define NT 2048
#define ND 1024
#define NH 64
#define SPL 4

typedef unsigned long long ull;

__device__ __forceinline__ uint32_t f2tf32(float f) {
    uint32_t u; asm("cvt.rna.tf32.f32 %0, %1;" : "=r"(u) : "f"(f)); return u;
}
__device__ __forceinline__ float tf32f(float f) {
    return __uint_as_float(f2tf32(f));
}
__device__ __forceinline__ float4 tf32f4(float4 v) {
    return make_float4(tf32f(v.x), tf32f(v.y), tf32f(v.z), tf32f(v.w));
}

#define MMA_TF32(D, A0, A1, A2, A3, B0, B1)                                   \
    asm volatile(                                                             \
        "mma.sync.aligned.m16n8k8.row.col.f32.tf32.tf32.f32 "                 \
        "{%0,%1,%2,%3}, {%4,%5,%6,%7}, {%8,%9}, {%0,%1,%2,%3};"               \
        : "+f"((D)[0]), "+f"((D)[1]), "+f"((D)[2]), "+f"((D)[3])              \
        : "r"(A0), "r"(A1), "r"(A2), "r"(A3), "r"(B0), "r"(B1))

// Q,K,V row-major [b][t][h]; split-K partials.
__device__ float g_q [NB * NT * NH];
__device__ float g_k [NB * NT * NH];
__device__ float g_v [NB * NT * NH];
__device__ float g_po[(size_t)NB * NT * SPL * NH];
__device__ float g_pm[NB * NT * SPL];
__device__ float g_pl[NB * NT * SPL];

// ---------------------------------------------------------------------------
// Projection via mma.sync tf32. Block tile 32 rows x 192 cols (q|k|v fused),
// 128 threads / 4 warps, warp tile 32x48 (m=2, n=6): 20 LDS-wf per 12 MMAs.
// A stride 36 -> fragment bank = 4g+t, conflict-free. B stride 200 ->
// bank = 8t+g, conflict-free. BK=32 double-buffered, reg-staged prefetch.
// ---------------------------------------------------------------------------
#define PJ_ASTR 36
#define PJ_BSTR 200
#define PJ_AS (32 * PJ_ASTR)
#define PJ_BS (32 * PJ_BSTR)
#define PJ_BUF (PJ_AS + PJ_BS)
#define PJ_SMEM_BYTES (2 * PJ_BUF * 4)   // 60416 B

__global__ __launch_bounds__(128) void proj_mma(
    const float* __restrict__ x, const float* __restrict__ Wq,
    const float* __restrict__ Wk, const float* __restrict__ Wv,
    const int* __restrict__ valid_lens)
{
    extern __shared__ float pjs[];
    const int b  = blockIdx.y;
    const int t0 = blockIdx.x * 32;
    int L = valid_lens[b];
    if (L < 0) L = 0;
    if (L > NT) L = NT;
    if (t0 >= L) return;

    const int tid  = threadIdx.x;
    const int lane = tid & 31;
    const int wid  = tid >> 5;       // 0..3
    const int g    = lane >> 2;
    const int t    = lane & 3;
    const int col0 = wid * 48;       // warp column base

    const float* Wm[3] = { Wq, Wk, Wv };
    const int ar  = tid >> 2;        // A row 0..31
    const int ak8 = (tid & 3) * 8;   // A k base 0,8,16,24 (two float4s)

    float d[2][6][4];
    #pragma unroll
    for (int mt = 0; mt < 2; mt++)
        #pragma unroll
        for (int nt = 0; nt < 6; nt++)
            #pragma unroll
            for (int e = 0; e < 4; e++) d[mt][nt][e] = 0.f;

    // preload chunk 0
    {
        float* As = pjs;
        float* Bs = pjs + PJ_AS;
        const float* xr = &x[((size_t)b * NT + t0 + ar) * ND];
        *(float4*)&As[ar * PJ_ASTR + ak8]     = tf32f4(*(const float4*)&xr[ak8]);
        *(float4*)&As[ar * PJ_ASTR + ak8 + 4] = tf32f4(*(const float4*)&xr[ak8 + 4]);
        #pragma unroll
        for (int i = 0; i < 12; i++) {
            int idx = tid + 128 * i;       // 0..1535
            int k   = idx / 48;
            int c4  = (idx % 48) * 4;      // 0..188
            float4 w = *(const float4*)&Wm[c4 >> 6][(size_t)k * NH + (c4 & 63)];
            *(float4*)&Bs[k * PJ_BSTR + c4] = tf32f4(w);
        }
    }
    __syncthreads();

    int buf = 0;
    for (int c = 0; c < 32; c++) {
        const int kb = c * 32;
        const bool has_next = (c < 31);
        float4 pa0, pa1, pb[12];
        if (has_next) {
            const float* xr = &x[((size_t)b * NT + t0 + ar) * ND + kb + 32];
            pa0 = *(const float4*)&xr[ak8];
            pa1 = *(const float4*)&xr[ak8 + 4];
            #pragma unroll
            for (int i = 0; i < 12; i++) {
                int idx = tid + 128 * i;
                int k   = idx / 48;
                int c4  = (idx % 48) * 4;
                pb[i] = *(const float4*)&Wm[c4 >> 6][(size_t)(kb + 32 + k) * NH + (c4 & 63)];
            }
        }

        const float* As = pjs + buf * PJ_BUF;
        const float* Bs = As + PJ_AS;
        #pragma unroll
        for (int k8 = 0; k8 < 4; k8++) {
            const int kc = k8 * 8 + t;
            uint32_t afr[2][4];
            #pragma unroll
            for (int mt = 0; mt < 2; mt++) {
                const int r0 = mt * 16 + g;
                afr[mt][0] = __float_as_uint(As[r0 * PJ_ASTR + kc]);
                afr[mt][1] = __float_as_uint(As[(r0 + 8) * PJ_ASTR + kc]);
                afr[mt][2] = __float_as_uint(As[r0 * PJ_ASTR + kc + 4]);
                afr[mt][3] = __float_as_uint(As[(r0 + 8) * PJ_ASTR + kc + 4]);
            }
            #pragma unroll
            for (int nt = 0; nt < 6; nt++) {
                const int n = col0 + nt * 8 + g;
                uint32_t b0 = __float_as_uint(Bs[kc * PJ_BSTR + n]);
                uint32_t b1 = __float_as_uint(Bs[(kc + 4) * PJ_BSTR + n]);
                #pragma unroll
                for (int mt = 0; mt < 2; mt++)
                    MMA_TF32(d[mt][nt], afr[mt][0], afr[mt][1], afr[mt][2], afr[mt][3], b0, b1);
            }
        }

        if (has_next) {
            float* As2 = pjs + (buf ^ 1) * PJ_BUF;
            float* Bs2 = As2 + PJ_AS;
            *(float4*)&As2[ar * PJ_ASTR + ak8]     = tf32f4(pa0);
            *(float4*)&As2[ar * PJ_ASTR + ak8 + 4] = tf32f4(pa1);
            #pragma unroll
            for (int i = 0; i < 12; i++) {
                int idx = tid + 128 * i;
                int k   = idx / 48;
                int c4  = (idx % 48) * 4;
                *(float4*)&Bs2[k * PJ_BSTR + c4] = tf32f4(pb[i]);
            }
        }
        __syncthreads();
        buf ^= 1;
    }

    // epilogue: stage [32 rows][stride 200], coalesced stores
    float* sm2 = pjs;
    #pragma unroll
    for (int mt = 0; mt < 2; mt++)
        #pragma unroll
        for (int nt = 0; nt < 6; nt++)
            #pragma unroll
            for (int e = 0; e < 4; e += 2) {
                const int r  = mt * 16 + g + ((e >= 2) ? 8 : 0);
                const int cc = col0 + nt * 8 + 2 * t;
                *(float2*)&sm2[r * PJ_BSTR + cc] = make_float2(d[mt][nt][e], d[mt][nt][e + 1]);
            }
    __syncthreads();

    #pragma unroll
    for (int i = 0; i < 12; i++) {
        int idx = tid + 128 * i;          // 0..1535
        int r   = idx / 48;
        int c4  = (idx % 48) * 4;
        float4 v = *(const float4*)&sm2[r * PJ_BSTR + c4];
        float* __restrict__ O = (c4 < 64) ? g_q : ((c4 < 128) ? g_k : g_v);
        *(float4*)&O[((size_t)b * NT + t0 + r) * NH + (c4 & 63)] = v;
    }
}

// ---------------------------------------------------------------------------
// Tensor-core flash attention partials. BQ=128, BK=64, 256 thr / 8 warps,
// SPL=4 split-K. (measured-best version, verbatim)
// ---------------------------------------------------------------------------
#define BQ 128
#define AT_QP 0
#define AT_KS (128 * 68)
#define AT_VS (AT_KS + 64 * 68)
#define AT_FLOATS (AT_VS + 64 * 68)
#define AT_BYTES (AT_FLOATS * 4)

__global__ __launch_bounds__(256, 2) void attn_part(const int* __restrict__ valid_lens)
{
    extern __shared__ float sm[];
    const int b  = blockIdx.y;
    const int q0 = blockIdx.x * BQ;
    const int s  = blockIdx.z;
    int L = valid_lens[b];
    if (L < 0) L = 0;
    if (L > NT) L = NT;
    if (q0 >= L) return;

    const int tid  = threadIdx.x;
    const int lane = tid & 31;
    const int w    = tid >> 5;
    const int g    = lane >> 2;
    const int t    = lane & 3;
    const int r0   = w * 16 + g;

    const int kend = (q0 + BQ < L) ? (q0 + BQ) : L;
    const int C  = (((kend + SPL - 1) / SPL) + 63) & ~63;
    const int jb = s * C;
    const int je = (jb + C < kend) ? (jb + C) : kend;

    if (jb >= je) {
        const float4 z4 = make_float4(0.f, 0.f, 0.f, 0.f);
        #pragma unroll
        for (int i = 0; i < 8; i++) {
            int idx = tid + 256 * i;
            int row = idx >> 4, h4 = (idx & 15) * 4;
            *(float4*)&g_po[((size_t)(b * NT + q0 + row) * SPL + s) * NH + h4] = z4;
        }
        if (tid < BQ) {
            g_pm[(size_t)(b * NT + q0 + tid) * SPL + s] = -1e30f;
            g_pl[(size_t)(b * NT + q0 + tid) * SPL + s] = 0.f;
        }
        return;
    }

    #pragma unroll
    for (int i = 0; i < 8; i++) {
        int idx = tid + 256 * i;
        int r = idx >> 4, c4 = (idx & 15) * 4;
        float4 v = *(const float4*)&g_q[((size_t)b * NT + q0 + r) * NH + c4];
        sm[AT_QP + r * 68 + c4 + 0] = tf32f(v.x);
        sm[AT_QP + r * 68 + c4 + 1] = tf32f(v.y);
        sm[AT_QP + r * 68 + c4 + 2] = tf32f(v.z);
        sm[AT_QP + r * 68 + c4 + 3] = tf32f(v.w);
    }
    __syncthreads();

    uint32_t qf[8][4];
    #pragma unroll
    for (int kc = 0; kc < 8; kc++) {
        const int k0 = kc * 8;
        qf[kc][0] = __float_as_uint(sm[AT_QP + r0 * 68 + k0 + t]);
        qf[kc][1] = __float_as_uint(sm[AT_QP + (r0 + 8) * 68 + k0 + t]);
        qf[kc][2] = __float_as_uint(sm[AT_QP + r0 * 68 + k0 + t + 4]);
        qf[kc][3] = __float_as_uint(sm[AT_QP + (r0 + 8) * 68 + k0 + t + 4]);
    }
    __syncthreads();

    float m0 = -1e30f, m1 = -1e30f, l0 = 0.f, l1 = 0.f;
    float o[8][4];
    #pragma unroll
    for (int nt = 0; nt < 8; nt++)
        #pragma unroll
        for (int e = 0; e < 4; e++) o[nt][e] = 0.f;

    for (int j0 = jb; j0 < je; j0 += 64) {
        __syncthreads();
        #pragma unroll
        for (int i = 0; i < 4; i++) {
            int idx = tid + 256 * i;
            int r = idx >> 4, c4 = (idx & 15) * 4;
            float4 kv = *(const float4*)&g_k[((size_t)b * NT + j0 + r) * NH + c4];
            float4 vv = *(const float4*)&g_v[((size_t)b * NT + j0 + r) * NH + c4];
            sm[AT_KS + r * 68 + c4 + 0] = tf32f(kv.x);
            sm[AT_KS + r * 68 + c4 + 1] = tf32f(kv.y);
            sm[AT_KS + r * 68 + c4 + 2] = tf32f(kv.z);
            sm[AT_KS + r * 68 + c4 + 3] = tf32f(kv.w);
            sm[AT_VS + r * 68 + c4 + 0] = tf32f(vv.x);
            sm[AT_VS + r * 68 + c4 + 1] = tf32f(vv.y);
            sm[AT_VS + r * 68 + c4 + 2] = tf32f(vv.z);
            sm[AT_VS + r * 68 + c4 + 3] = tf32f(vv.w);
        }
        __syncthreads();

        float sv[8][4];
        #pragma unroll
        for (int nt = 0; nt < 8; nt++)
            #pragma unroll
            for (int e = 0; e < 4; e++) sv[nt][e] = 0.f;

        #pragma unroll
        for (int kc = 0; kc < 8; kc++) {
            const int k0 = kc * 8;
            #pragma unroll
            for (int nt = 0; nt < 8; nt++) {
                const int n = nt * 8 + g;
                uint32_t b0 = __float_as_uint(sm[AT_KS + n * 68 + k0 + t]);
                uint32_t b1 = __float_as_uint(sm[AT_KS + n * 68 + k0 + t + 4]);
                MMA_TF32(sv[nt], qf[kc][0], qf[kc][1], qf[kc][2], qf[kc][3], b0, b1);
            }
        }

        const int qg0 = q0 + r0;
        const int qg1 = qg0 + 8;
        #pragma unroll
        for (int nt = 0; nt < 8; nt++) {
            #pragma unroll
            for (int e = 0; e < 4; e++) {
                const int key = j0 + nt * 8 + 2 * t + (e & 1);
                const int q   = (e & 2) ? qg1 : qg0;
                const bool valid = (key <= q) && (key < L);
                sv[nt][e] = valid ? sv[nt][e] * 0.125f : -1e30f;
            }
        }

        float tm0 = -1e30f, tm1 = -1e30f;
        #pragma unroll
        for (int nt = 0; nt < 8; nt++) {
            tm0 = fmaxf(tm0, fmaxf(sv[nt][0], sv[nt][1]));
            tm1 = fmaxf(tm1, fmaxf(sv[nt][2], sv[nt][3]));
        }
        #pragma unroll
        for (int off = 1; off < 4; off <<= 1) {
            tm0 = fmaxf(tm0, __shfl_xor_sync(0xffffffffu, tm0, off));
            tm1 = fmaxf(tm1, __shfl_xor_sync(0xffffffffu, tm1, off));
        }
        const float mn0 = fmaxf(m0, tm0), mn1 = fmaxf(m1, tm1);
        const float corr0 = __expf(m0 - mn0), corr1 = __expf(m1 - mn1);

        float ps0 = 0.f, ps1 = 0.f;
        float pv[8][4];
        #pragma unroll
        for (int nt = 0; nt < 8; nt++) {
            pv[nt][0] = (sv[nt][0] > -1e29f) ? __expf(sv[nt][0] - mn0) : 0.f;
            pv[nt][1] = (sv[nt][1] > -1e29f) ? __expf(sv[nt][1] - mn0) : 0.f;
            pv[nt][2] = (sv[nt][2] > -1e29f) ? __expf(sv[nt][2] - mn1) : 0.f;
            pv[nt][3] = (sv[nt][3] > -1e29f) ? __expf(sv[nt][3] - mn1) : 0.f;
            ps0 += pv[nt][0] + pv[nt][1];
            ps1 += pv[nt][2] + pv[nt][3];
        }
        #pragma unroll
        for (int off = 1; off < 4; off <<= 1) {
            ps0 += __shfl_xor_sync(0xffffffffu, ps0, off);
            ps1 += __shfl_xor_sync(0xffffffffu, ps1, off);
        }
        l0 = l0 * corr0 + ps0; m0 = mn0;
        l1 = l1 * corr1 + ps1; m1 = mn1;

        #pragma unroll
        for (int nt = 0; nt < 8; nt++) {
            o[nt][0] *= corr0; o[nt][1] *= corr0;
            o[nt][2] *= corr1; o[nt][3] *= corr1;
            const int cc = nt * 8 + 2 * t;
            sm[AT_QP + r0 * 68 + cc]           = tf32f(pv[nt][0]);
            sm[AT_QP + r0 * 68 + cc + 1]       = tf32f(pv[nt][1]);
            sm[AT_QP + (r0 + 8) * 68 + cc]     = tf32f(pv[nt][2]);
            sm[AT_QP + (r0 + 8) * 68 + cc + 1] = tf32f(pv[nt][3]);
        }
        __syncwarp();

        #pragma unroll
        for (int kc = 0; kc < 8; kc++) {
            const int k0 = kc * 8;
            uint32_t a0 = __float_as_uint(sm[AT_QP + r0 * 68 + k0 + t]);
            uint32_t a1 = __float_as_uint(sm[AT_QP + (r0 + 8) * 68 + k0 + t]);
            uint32_t a2 = __float_as_uint(sm[AT_QP + r0 * 68 + k0 + t + 4]);
            uint32_t a3 = __float_as_uint(sm[AT_QP + (r0 + 8) * 68 + k0 + t + 4]);
            #pragma unroll
            for (int nt = 0; nt < 8; nt++) {
                const int n = nt * 8 + g;
                uint32_t b0 = __float_as_uint(sm[AT_VS + (k0 + t) * 68 + n]);
                uint32_t b1 = __float_as_uint(sm[AT_VS + (k0 + t + 4) * 68 + n]);
                MMA_TF32(o[nt], a0, a1, a2, a3, b0, b1);
            }
        }
        __syncwarp();
    }

    const size_t pr0 = ((size_t)(b * NT + q0 + r0) * SPL + s);
    const size_t pr1 = ((size_t)(b * NT + q0 + r0 + 8) * SPL + s);
    #pragma unroll
    for (int nt = 0; nt < 8; nt++) {
        const int cc = nt * 8 + 2 * t;
        *(float2*)&g_po[pr0 * NH + cc] = make_float2(o[nt][0], o[nt][1]);
        *(float2*)&g_po[pr1 * NH + cc] = make_float2(o[nt][2], o[nt][3]);
    }
    if (t == 0) {
        g_pm[pr0] = m0; g_pl[pr0] = l0;
        g_pm[pr1] = m1; g_pl[pr1] = l1;
    }
}

// ---------------------------------------------------------------------------
// Combine split-K partials.
// ---------------------------------------------------------------------------
__global__ __launch_bounds__(128) void attn_combine(
    const int* __restrict__ valid_lens, float* __restrict__ out)
{
    const int b   = blockIdx.y;
    const int tid = threadIdx.x;
    const int row = tid >> 3;
    const int t8  = tid & 7;
    const int q   = blockIdx.x * 16 + row;
    int L = valid_lens[b];
    if (L < 0) L = 0;
    if (L > NT) L = NT;

    const size_t base0 = (size_t)(b * NT + q) * SPL;
    float ms[SPL], mstar = -1e30f;
    #pragma unroll
    for (int s = 0; s < SPL; s++) {
        ms[s] = g_pm[base0 + s];
        mstar = fmaxf(mstar, ms[s]);
    }
    float l = 0.f;
    float4 oA = make_float4(0.f, 0.f, 0.f, 0.f);
    float4 oB = make_float4(0.f, 0.f, 0.f, 0.f);
    #pragma unroll
    for (int s = 0; s < SPL; s++) {
        const float w = (ms[s] > -1e29f) ? __expf(ms[s] - mstar) : 0.f;
        l += g_pl[base0 + s] * w;
        float4 a = *(const float4*)&g_po[(base0 + s) * NH + t8 * 4];
        float4 c = *(const float4*)&g_po[(base0 + s) * NH + 32 + t8 * 4];
        oA.x += a.x * w; oA.y += a.y * w; oA.z += a.z * w; oA.w += a.w * w;
        oB.x += c.x * w; oB.y += c.y * w; oB.z += c.z * w; oB.w += c.w * w;
    }
    const float inv = (q < L && l > 0.f) ? (1.f / l) : 0.f;
    const size_t ob = ((size_t)b * NT + q) * NH;
    *(float4*)&out[ob + t8 * 4] =
        make_float4(oA.x * inv, oA.y * inv, oA.z * inv, oA.w * inv);
    *(float4*)&out[ob + 32 + t8 * 4] =
        make_float4(oB.x * inv, oB.y * inv, oB.z * inv, oB.w * inv);
}

extern "C" void kernel_launch(void* const* d_in, const int* in_sizes, int n_in,
                              void* d_out, int out_size)
{
    const float* x  = (const float*)d_in[0];
    const float* Wq = (const float*)d_in[1];
    const float* Wk = (const float*)d_in[2];
    const float* Wv = (const float*)d_in[3];
    const int*   vl = (const int*)d_in[4];
    float* out = (float*)d_out;

    cudaFuncSetAttribute(proj_mma, cudaFuncAttributeMaxDynamicSharedMemorySize, PJ_SMEM_BYTES);
    cudaFuncSetAttribute(attn_part, cudaFuncAttributeMaxDynamicSharedMemorySize, AT_BYTES);

    proj_mma<<<dim3(NT / 32, NB), 128, PJ_SMEM_BYTES>>>(x, Wq, Wk, Wv, vl);
    attn_part<<<dim3(NT / BQ, NB, SPL), 256, AT_BYTES>>>(vl);
    attn_combine<<<dim3(NT / 16, NB), 128>>>(vl, out);
}

// round 17
// speedup vs baseline: 1.1454x; 1.1454x over previous
#include <cuda_runtime.h>
#include <cstdint>

#define NB 8
#define NT 2048
#define ND 1024
#define NH 64
#define SPL 4

typedef unsigned long long ull;

__device__ __forceinline__ uint32_t f2tf32(float f) {
    uint32_t u; asm("cvt.rna.tf32.f32 %0, %1;" : "=r"(u) : "f"(f)); return u;
}
__device__ __forceinline__ float tf32f(float f) {
    return __uint_as_float(f2tf32(f));
}
__device__ __forceinline__ float4 tf32f4(float4 v) {
    return make_float4(tf32f(v.x), tf32f(v.y), tf32f(v.z), tf32f(v.w));
}

#define MMA_TF32(D, A0, A1, A2, A3, B0, B1)                                   \
    asm volatile(                                                             \
        "mma.sync.aligned.m16n8k8.row.col.f32.tf32.tf32.f32 "                 \
        "{%0,%1,%2,%3}, {%4,%5,%6,%7}, {%8,%9}, {%0,%1,%2,%3};"               \
        : "+f"((D)[0]), "+f"((D)[1]), "+f"((D)[2]), "+f"((D)[3])              \
        : "r"(A0), "r"(A1), "r"(A2), "r"(A3), "r"(B0), "r"(B1))

// Q,K,V row-major [b][t][h]; split-K partials.
__device__ float g_q [NB * NT * NH];
__device__ float g_k [NB * NT * NH];
__device__ float g_v [NB * NT * NH];
__device__ float g_po[(size_t)NB * NT * SPL * NH];
__device__ float g_pm[NB * NT * SPL];
__device__ float g_pl[NB * NT * SPL];

// ---------------------------------------------------------------------------
// Projection via mma.sync tf32. Block tile 32 rows x 192 cols (q|k|v fused),
// 256 threads / 8 warps, warp tile 32x24 (m=2, n=3). BK=32 double-buffered.
// A stride 36: fragment bank = 4g+t, conflict-free (was 2-way at 40).
// B stride 200: fragment bank = 8t+g, conflict-free.
// ---------------------------------------------------------------------------
#define PJ_ASTR 36
#define PJ_BSTR 200
#define PJ_AS (32 * PJ_ASTR)
#define PJ_BS (32 * PJ_BSTR)
#define PJ_BUF (PJ_AS + PJ_BS)
#define PJ_SMEM_BYTES (2 * PJ_BUF * 4)

__global__ __launch_bounds__(256) void proj_mma(
    const float* __restrict__ x, const float* __restrict__ Wq,
    const float* __restrict__ Wk, const float* __restrict__ Wv,
    const int* __restrict__ valid_lens)
{
    extern __shared__ float pjs[];
    const int b  = blockIdx.y;
    const int t0 = blockIdx.x * 32;
    int L = valid_lens[b];
    if (L < 0) L = 0;
    if (L > NT) L = NT;
    if (t0 >= L) return;

    const int tid  = threadIdx.x;
    const int lane = tid & 31;
    const int wid  = tid >> 5;
    const int g    = lane >> 2;
    const int t    = lane & 3;
    const int col0 = wid * 24;      // warp column base (0..168)

    const float* Wm[3] = { Wq, Wk, Wv };
    const int ar  = tid >> 3;       // A row 0..31
    const int ak4 = (tid & 7) * 4;  // A k 0..28

    float d[2][3][4];
    #pragma unroll
    for (int mt = 0; mt < 2; mt++)
        #pragma unroll
        for (int nt = 0; nt < 3; nt++)
            #pragma unroll
            for (int e = 0; e < 4; e++) d[mt][nt][e] = 0.f;

    // preload chunk 0
    {
        float* As = pjs;
        float* Bs = pjs + PJ_AS;
        float4 v = *(const float4*)&x[((size_t)b * NT + t0 + ar) * ND + ak4];
        *(float4*)&As[ar * PJ_ASTR + ak4] = tf32f4(v);
        #pragma unroll
        for (int i = 0; i < 6; i++) {
            int idx = tid + 256 * i;       // 0..1535
            int k   = idx / 48;
            int c4  = (idx % 48) * 4;      // 0..188
            float4 w = *(const float4*)&Wm[c4 >> 6][(size_t)k * NH + (c4 & 63)];
            *(float4*)&Bs[k * PJ_BSTR + c4] = tf32f4(w);
        }
    }
    __syncthreads();

    int buf = 0;
    for (int c = 0; c < 32; c++) {
        const int kb = c * 32;
        const bool has_next = (c < 31);
        float4 pa, pb[6];
        if (has_next) {
            pa = *(const float4*)&x[((size_t)b * NT + t0 + ar) * ND + kb + 32 + ak4];
            #pragma unroll
            for (int i = 0; i < 6; i++) {
                int idx = tid + 256 * i;
                int k   = idx / 48;
                int c4  = (idx % 48) * 4;
                pb[i] = *(const float4*)&Wm[c4 >> 6][(size_t)(kb + 32 + k) * NH + (c4 & 63)];
            }
        }

        const float* As = pjs + buf * PJ_BUF;
        const float* Bs = As + PJ_AS;
        #pragma unroll
        for (int k8 = 0; k8 < 4; k8++) {
            const int kc = k8 * 8 + t;
            uint32_t afr[2][4];
            #pragma unroll
            for (int mt = 0; mt < 2; mt++) {
                const int r0 = mt * 16 + g;
                afr[mt][0] = __float_as_uint(As[r0 * PJ_ASTR + kc]);
                afr[mt][1] = __float_as_uint(As[(r0 + 8) * PJ_ASTR + kc]);
                afr[mt][2] = __float_as_uint(As[r0 * PJ_ASTR + kc + 4]);
                afr[mt][3] = __float_as_uint(As[(r0 + 8) * PJ_ASTR + kc + 4]);
            }
            #pragma unroll
            for (int nt = 0; nt < 3; nt++) {
                const int n = col0 + nt * 8 + g;
                uint32_t b0 = __float_as_uint(Bs[kc * PJ_BSTR + n]);
                uint32_t b1 = __float_as_uint(Bs[(kc + 4) * PJ_BSTR + n]);
                #pragma unroll
                for (int mt = 0; mt < 2; mt++)
                    MMA_TF32(d[mt][nt], afr[mt][0], afr[mt][1], afr[mt][2], afr[mt][3], b0, b1);
            }
        }

        if (has_next) {
            float* As2 = pjs + (buf ^ 1) * PJ_BUF;
            float* Bs2 = As2 + PJ_AS;
            *(float4*)&As2[ar * PJ_ASTR + ak4] = tf32f4(pa);
            #pragma unroll
            for (int i = 0; i < 6; i++) {
                int idx = tid + 256 * i;
                int k   = idx / 48;
                int c4  = (idx % 48) * 4;
                *(float4*)&Bs2[k * PJ_BSTR + c4] = tf32f4(pb[i]);
            }
        }
        __syncthreads();
        buf ^= 1;
    }

    // epilogue: stage [32 rows][stride 200], coalesced stores
    float* sm2 = pjs;
    #pragma unroll
    for (int mt = 0; mt < 2; mt++)
        #pragma unroll
        for (int nt = 0; nt < 3; nt++)
            #pragma unroll
            for (int e = 0; e < 4; e += 2) {
                const int r  = mt * 16 + g + ((e >= 2) ? 8 : 0);
                const int cc = col0 + nt * 8 + 2 * t;
                *(float2*)&sm2[r * PJ_BSTR + cc] = make_float2(d[mt][nt][e], d[mt][nt][e + 1]);
            }
    __syncthreads();

    #pragma unroll
    for (int i = 0; i < 6; i++) {
        int idx = tid + 256 * i;          // 0..1535
        int r   = idx / 48;
        int c4  = (idx % 48) * 4;
        float4 v = *(const float4*)&sm2[r * PJ_BSTR + c4];
        float* __restrict__ O = (c4 < 64) ? g_q : ((c4 < 128) ? g_k : g_v);
        *(float4*)&O[((size_t)b * NT + t0 + r) * NH + (c4 & 63)] = v;
    }
}

// ---------------------------------------------------------------------------
// Tensor-core flash attention partials. BQ=128, BK=64, 256 thr / 8 warps,
// SPL=4 split-K. (measured-best version, verbatim)
// ---------------------------------------------------------------------------
#define BQ 128
#define AT_QP 0
#define AT_KS (128 * 68)
#define AT_VS (AT_KS + 64 * 68)
#define AT_FLOATS (AT_VS + 64 * 68)
#define AT_BYTES (AT_FLOATS * 4)

__global__ __launch_bounds__(256, 2) void attn_part(const int* __restrict__ valid_lens)
{
    extern __shared__ float sm[];
    const int b  = blockIdx.y;
    const int q0 = blockIdx.x * BQ;
    const int s  = blockIdx.z;
    int L = valid_lens[b];
    if (L < 0) L = 0;
    if (L > NT) L = NT;
    if (q0 >= L) return;

    const int tid  = threadIdx.x;
    const int lane = tid & 31;
    const int w    = tid >> 5;
    const int g    = lane >> 2;
    const int t    = lane & 3;
    const int r0   = w * 16 + g;

    const int kend = (q0 + BQ < L) ? (q0 + BQ) : L;
    const int C  = (((kend + SPL - 1) / SPL) + 63) & ~63;
    const int jb = s * C;
    const int je = (jb + C < kend) ? (jb + C) : kend;

    if (jb >= je) {
        const float4 z4 = make_float4(0.f, 0.f, 0.f, 0.f);
        #pragma unroll
        for (int i = 0; i < 8; i++) {
            int idx = tid + 256 * i;
            int row = idx >> 4, h4 = (idx & 15) * 4;
            *(float4*)&g_po[((size_t)(b * NT + q0 + row) * SPL + s) * NH + h4] = z4;
        }
        if (tid < BQ) {
            g_pm[(size_t)(b * NT + q0 + tid) * SPL + s] = -1e30f;
            g_pl[(size_t)(b * NT + q0 + tid) * SPL + s] = 0.f;
        }
        return;
    }

    #pragma unroll
    for (int i = 0; i < 8; i++) {
        int idx = tid + 256 * i;
        int r = idx >> 4, c4 = (idx & 15) * 4;
        float4 v = *(const float4*)&g_q[((size_t)b * NT + q0 + r) * NH + c4];
        sm[AT_QP + r * 68 + c4 + 0] = tf32f(v.x);
        sm[AT_QP + r * 68 + c4 + 1] = tf32f(v.y);
        sm[AT_QP + r * 68 + c4 + 2] = tf32f(v.z);
        sm[AT_QP + r * 68 + c4 + 3] = tf32f(v.w);
    }
    __syncthreads();

    uint32_t qf[8][4];
    #pragma unroll
    for (int kc = 0; kc < 8; kc++) {
        const int k0 = kc * 8;
        qf[kc][0] = __float_as_uint(sm[AT_QP + r0 * 68 + k0 + t]);
        qf[kc][1] = __float_as_uint(sm[AT_QP + (r0 + 8) * 68 + k0 + t]);
        qf[kc][2] = __float_as_uint(sm[AT_QP + r0 * 68 + k0 + t + 4]);
        qf[kc][3] = __float_as_uint(sm[AT_QP + (r0 + 8) * 68 + k0 + t + 4]);
    }
    __syncthreads();

    float m0 = -1e30f, m1 = -1e30f, l0 = 0.f, l1 = 0.f;
    float o[8][4];
    #pragma unroll
    for (int nt = 0; nt < 8; nt++)
        #pragma unroll
        for (int e = 0; e < 4; e++) o[nt][e] = 0.f;

    for (int j0 = jb; j0 < je; j0 += 64) {
        __syncthreads();
        #pragma unroll
        for (int i = 0; i < 4; i++) {
            int idx = tid + 256 * i;
            int r = idx >> 4, c4 = (idx & 15) * 4;
            float4 kv = *(const float4*)&g_k[((size_t)b * NT + j0 + r) * NH + c4];
            float4 vv = *(const float4*)&g_v[((size_t)b * NT + j0 + r) * NH + c4];
            sm[AT_KS + r * 68 + c4 + 0] = tf32f(kv.x);
            sm[AT_KS + r * 68 + c4 + 1] = tf32f(kv.y);
            sm[AT_KS + r * 68 + c4 + 2] = tf32f(kv.z);
            sm[AT_KS + r * 68 + c4 + 3] = tf32f(kv.w);
            sm[AT_VS + r * 68 + c4 + 0] = tf32f(vv.x);
            sm[AT_VS + r * 68 + c4 + 1] = tf32f(vv.y);
            sm[AT_VS + r * 68 + c4 + 2] = tf32f(vv.z);
            sm[AT_VS + r * 68 + c4 + 3] = tf32f(vv.w);
        }
        __syncthreads();

        float sv[8][4];
        #pragma unroll
        for (int nt = 0; nt < 8; nt++)
            #pragma unroll
            for (int e = 0; e < 4; e++) sv[nt][e] = 0.f;

        #pragma unroll
        for (int kc = 0; kc < 8; kc++) {
            const int k0 = kc * 8;
            #pragma unroll
            for (int nt = 0; nt < 8; nt++) {
                const int n = nt * 8 + g;
                uint32_t b0 = __float_as_uint(sm[AT_KS + n * 68 + k0 + t]);
                uint32_t b1 = __float_as_uint(sm[AT_KS + n * 68 + k0 + t + 4]);
                MMA_TF32(sv[nt], qf[kc][0], qf[kc][1], qf[kc][2], qf[kc][3], b0, b1);
            }
        }

        const int qg0 = q0 + r0;
        const int qg1 = qg0 + 8;
        #pragma unroll
        for (int nt = 0; nt < 8; nt++) {
            #pragma unroll
            for (int e = 0; e < 4; e++) {
                const int key = j0 + nt * 8 + 2 * t + (e & 1);
                const int q   = (e & 2) ? qg1 : qg0;
                const bool valid = (key <= q) && (key < L);
                sv[nt][e] = valid ? sv[nt][e] * 0.125f : -1e30f;
            }
        }

        float tm0 = -1e30f, tm1 = -1e30f;
        #pragma unroll
        for (int nt = 0; nt < 8; nt++) {
            tm0 = fmaxf(tm0, fmaxf(sv[nt][0], sv[nt][1]));
            tm1 = fmaxf(tm1, fmaxf(sv[nt][2], sv[nt][3]));
        }
        #pragma unroll
        for (int off = 1; off < 4; off <<= 1) {
            tm0 = fmaxf(tm0, __shfl_xor_sync(0xffffffffu, tm0, off));
            tm1 = fmaxf(tm1, __shfl_xor_sync(0xffffffffu, tm1, off));
        }
        const float mn0 = fmaxf(m0, tm0), mn1 = fmaxf(m1, tm1);
        const float corr0 = __expf(m0 - mn0), corr1 = __expf(m1 - mn1);

        float ps0 = 0.f, ps1 = 0.f;
        float pv[8][4];
        #pragma unroll
        for (int nt = 0; nt < 8; nt++) {
            pv[nt][0] = (sv[nt][0] > -1e29f) ? __expf(sv[nt][0] - mn0) : 0.f;
            pv[nt][1] = (sv[nt][1] > -1e29f) ? __expf(sv[nt][1] - mn0) : 0.f;
            pv[nt][2] = (sv[nt][2] > -1e29f) ? __expf(sv[nt][2] - mn1) : 0.f;
            pv[nt][3] = (sv[nt][3] > -1e29f) ? __expf(sv[nt][3] - mn1) : 0.f;
            ps0 += pv[nt][0] + pv[nt][1];
            ps1 += pv[nt][2] + pv[nt][3];
        }
        #pragma unroll
        for (int off = 1; off < 4; off <<= 1) {
            ps0 += __shfl_xor_sync(0xffffffffu, ps0, off);
            ps1 += __shfl_xor_sync(0xffffffffu, ps1, off);
        }
        l0 = l0 * corr0 + ps0; m0 = mn0;
        l1 = l1 * corr1 + ps1; m1 = mn1;

        #pragma unroll
        for (int nt = 0; nt < 8; nt++) {
            o[nt][0] *= corr0; o[nt][1] *= corr0;
            o[nt][2] *= corr1; o[nt][3] *= corr1;
            const int cc = nt * 8 + 2 * t;
            sm[AT_QP + r0 * 68 + cc]           = tf32f(pv[nt][0]);
            sm[AT_QP + r0 * 68 + cc + 1]       = tf32f(pv[nt][1]);
            sm[AT_QP + (r0 + 8) * 68 + cc]     = tf32f(pv[nt][2]);
            sm[AT_QP + (r0 + 8) * 68 + cc + 1] = tf32f(pv[nt][3]);
        }
        __syncwarp();

        #pragma unroll
        for (int kc = 0; kc < 8; kc++) {
            const int k0 = kc * 8;
            uint32_t a0 = __float_as_uint(sm[AT_QP + r0 * 68 + k0 + t]);
            uint32_t a1 = __float_as_uint(sm[AT_QP + (r0 + 8) * 68 + k0 + t]);
            uint32_t a2 = __float_as_uint(sm[AT_QP + r0 * 68 + k0 + t + 4]);
            uint32_t a3 = __float_as_uint(sm[AT_QP + (r0 + 8) * 68 + k0 + t + 4]);
            #pragma unroll
            for (int nt = 0; nt < 8; nt++) {
                const int n = nt * 8 + g;
                uint32_t b0 = __float_as_uint(sm[AT_VS + (k0 + t) * 68 + n]);
                uint32_t b1 = __float_as_uint(sm[AT_VS + (k0 + t + 4) * 68 + n]);
                MMA_TF32(o[nt], a0, a1, a2, a3, b0, b1);
            }
        }
        __syncwarp();
    }

    const size_t pr0 = ((size_t)(b * NT + q0 + r0) * SPL + s);
    const size_t pr1 = ((size_t)(b * NT + q0 + r0 + 8) * SPL + s);
    #pragma unroll
    for (int nt = 0; nt < 8; nt++) {
        const int cc = nt * 8 + 2 * t;
        *(float2*)&g_po[pr0 * NH + cc] = make_float2(o[nt][0], o[nt][1]);
        *(float2*)&g_po[pr1 * NH + cc] = make_float2(o[nt][2], o[nt][3]);
    }
    if (t == 0) {
        g_pm[pr0] = m0; g_pl[pr0] = l0;
        g_pm[pr1] = m1; g_pl[pr1] = l1;
    }
}

// ---------------------------------------------------------------------------
// Combine split-K partials.
// ---------------------------------------------------------------------------
__global__ __launch_bounds__(128) void attn_combine(
    const int* __restrict__ valid_lens, float* __restrict__ out)
{
    const int b   = blockIdx.y;
    const int tid = threadIdx.x;
    const int row = tid >> 3;
    const int t8  = tid & 7;
    const int q   = blockIdx.x * 16 + row;
    int L = valid_lens[b];
    if (L < 0) L = 0;
    if (L > NT) L = NT;

    const size_t base0 = (size_t)(b * NT + q) * SPL;
    float ms[SPL], mstar = -1e30f;
    #pragma unroll
    for (int s = 0; s < SPL; s++) {
        ms[s] = g_pm[base0 + s];
        mstar = fmaxf(mstar, ms[s]);
    }
    float l = 0.f;
    float4 oA = make_float4(0.f, 0.f, 0.f, 0.f);
    float4 oB = make_float4(0.f, 0.f, 0.f, 0.f);
    #pragma unroll
    for (int s = 0; s < SPL; s++) {
        const float w = (ms[s] > -1e29f) ? __expf(ms[s] - mstar) : 0.f;
        l += g_pl[base0 + s] * w;
        float4 a = *(const float4*)&g_po[(base0 + s) * NH + t8 * 4];
        float4 c = *(const float4*)&g_po[(base0 + s) * NH + 32 + t8 * 4];
        oA.x += a.x * w; oA.y += a.y * w; oA.z += a.z * w; oA.w += a.w * w;
        oB.x += c.x * w; oB.y += c.y * w; oB.z += c.z * w; oB.w += c.w * w;
    }
    const float inv = (q < L && l > 0.f) ? (1.f / l) : 0.f;
    const size_t ob = ((size_t)b * NT + q) * NH;
    *(float4*)&out[ob + t8 * 4] =
        make_float4(oA.x * inv, oA.y * inv, oA.z * inv, oA.w * inv);
    *(float4*)&out[ob + 32 + t8 * 4] =
        make_float4(oB.x * inv, oB.y * inv, oB.z * inv, oB.w * inv);
}

extern "C" void kernel_launch(void* const* d_in, const int* in_sizes, int n_in,
                              void* d_out, int out_size)
{
    const float* x  = (const float*)d_in[0];
    const float* Wq = (const float*)d_in[1];
    const float* Wk = (const float*)d_in[2];
    const float* Wv = (const float*)d_in[3];
    const int*   vl = (const int*)d_in[4];
    float* out = (float*)d_out;

    cudaFuncSetAttribute(proj_mma, cudaFuncAttributeMaxDynamicSharedMemorySize, PJ_SMEM_BYTES);
    cudaFuncSetAttribute(attn_part, cudaFuncAttributeMaxDynamicSharedMemorySize, AT_BYTES);

    proj_mma<<<dim3(NT / 32, NB), 256, PJ_SMEM_BYTES>>>(x, Wq, Wk, Wv, vl);
    attn_part<<<dim3(NT / BQ, NB, SPL), 256, AT_BYTES>>>(vl);
    attn_combine<<<dim3(NT / 16, NB), 128>>>(vl, out);
}